// round 13
// baseline (speedup 1.0000x reference)
#include <cuda_runtime.h>
#include <math.h>

// Problem constants
#define NSHOT 4
#define NT    300
#define NRECV 100
#define NN    444          // padded grid (400 + 2*22)
#define SX    448          // row stride (zero pad cols 444..447)
#define FS    (NN*SX)      // per-shot plane: 198,912 floats
#define FIELD (NSHOT*FS)   // per field: 795,648 floats
#define PADC  16           // head pad floats (zero) before field 0
#define DTF   0.0005f
#define INVH  0.2f
#define INVH2 0.04f
#define C10 (1.0f/12.0f)
#define C11 (-2.0f/3.0f)
#define C13 (2.0f/3.0f)
#define C14 (-1.0f/12.0f)
#define C20 (-1.0f/12.0f)
#define C21 (4.0f/3.0f)
#define C22 (-2.5f)
#define OUT_SC    (NSHOT*444*444)
#define OUT_RECBG (2*NSHOT*444*444)
#define OUT_RECSC (OUT_RECBG + NSHOT*NRECV*NT)
#define SIGMA_MAX 259.0408229618301f
#define ALPHA_F   78.53981633974483f

// smem tile: 16 rows (8 output + 4 halo each side) x 136 cols (128 + 4 halo each side)
#define TROWS 16
#define TSX   136

// 16 state fields, contiguous:
// 0:WBG0 1:WBG1 2:WSC0 3:WSC1 4:PYB0 5:PYB1 6:PXB0 7:PXB1
// 8:PYS0 9:PYS1 10:PXS0 11:PXS1 12:ZYB 13:ZXB 14:ZYS 15:ZXS
__device__ __align__(256) float g_state[16*FIELD + 2*PADC];
__device__ __align__(256) float g_v2dt2[FS];
__device__ __align__(256) float g_born[FS];
__device__ float g_a[SX];
__device__ float g_b[SX];
__device__ float g_fbg[NSHOT*NT];
__device__ float g_fsc[NSHOT*NT];
__device__ int   g_sloc[NSHOT*2];

__global__ void zero_kernel() {
    const int n = 16*FIELD + 2*PADC;
    for (int i = blockIdx.x*blockDim.x + threadIdx.x; i < n; i += gridDim.x*blockDim.x)
        g_state[i] = 0.0f;
}

__global__ void init_kernel(const float* __restrict__ v, const float* __restrict__ sc,
                            const float* __restrict__ amp, const int* __restrict__ sloc) {
    int x = blockIdx.x*blockDim.x + threadIdx.x;   // 0..447
    int y = blockIdx.y;                            // 0..443
    if (x < NN) {
        int vy = min(max(y-22, 0), 399);
        int vx = min(max(x-22, 0), 399);
        float vv = v[vy*400 + vx];
        float ss = (y >= 22 && y < 422 && x >= 22 && x < 422) ? sc[(y-22)*400 + (x-22)] : 0.0f;
        g_v2dt2[y*SX+x] = (vv*DTF)*(vv*DTF);
        g_born [y*SX+x] = 2.0f*vv*ss*DTF*DTF;
    } else if (y < NN) {
        g_v2dt2[y*SX+x] = 0.0f;
        g_born [y*SX+x] = 0.0f;
    }
    if (y == 0) {
        float a = 0.0f, b = 0.0f;
        if (x < NN) {
            float fi = (float)x;
            float f1 = fminf(fmaxf((22.0f - fi)/20.0f, 0.0f), 1.0f);
            float f2 = fminf(fmaxf((fi - 421.0f)/20.0f, 0.0f), 1.0f);
            float frac = fmaxf(f1, f2);
            float sigma = SIGMA_MAX * frac * frac;
            a = expf(-(sigma + ALPHA_F)*DTF);
            b = (sigma > 0.0f) ? sigma/(sigma + ALPHA_F)*(a - 1.0f) : 0.0f;
        }
        g_a[x] = a; g_b[x] = b;
    }
    int lid = y*SX + x;
    if (lid < NSHOT*NT) {
        int s = lid / NT, t = lid % NT;
        int ly = sloc[s*2+0], lx = sloc[s*2+1];
        float vv = v [ly*400 + lx];
        float ss = sc[ly*400 + lx];
        float a  = amp[s*NT + t];
        g_fbg[lid] = (-a * (vv*vv)) * DTF * DTF;
        g_fsc[lid] = ((-2.0f * a) * (vv*ss)) * DTF * DTF;
    }
    if (lid < NSHOT*2) g_sloc[lid] = sloc[lid] + 22;
}

__device__ __forceinline__ void ld4(float* d, const float* p) {
    float4 t = __ldg(reinterpret_cast<const float4*>(p));
    d[0]=t.x; d[1]=t.y; d[2]=t.z; d[3]=t.w;
}
__device__ __forceinline__ void ld4z(float* d, const float* p, bool pred) {
    if (pred) ld4(d, p);
    else { d[0]=0.f; d[1]=0.f; d[2]=0.f; d[3]=0.f; }
}
__device__ __forceinline__ void st4(float* p, const float* d) {
    float4 t; t.x=d[0]; t.y=d[1]; t.z=d[2]; t.w=d[3];
    *reinterpret_cast<float4*>(p) = t;
}

// PML-Laplacian for a quad of 4 x-points of one field, stencil taps from smem.
// sw = smem tile; rc = &sw[r*TSX + c] where (r,c) are local coords of x0.
// psi/zeta traffic stays global.
__device__ __forceinline__ void lap_field4s(
    const float* __restrict__ sw, int r, int c,
    const float* __restrict__ py_o, float* __restrict__ py_n,
    const float* __restrict__ px_o, float* __restrict__ px_n,
    float* __restrict__ zy, float* __restrict__ zx,
    int bi, int y, int x0, bool pmly, bool pmlx, float lap[4])
{
    const float* rc = sw + r*TSX + c;
    float d2y[4], d2x[4];
    #pragma unroll
    for (int j = 0; j < 4; j++) {
        float w0 = rc[j];
        d2y[j] = INVH2*(C20*(rc[j-2*TSX]+rc[j+2*TSX]) + C21*(rc[j-TSX]+rc[j+TSX]) + C22*w0);
        d2x[j] = INVH2*(C20*(rc[j-2]+rc[j+2]) + C21*(rc[j-1]+rc[j+1]) + C22*w0);
        lap[j] = d2y[j] + d2x[j];
    }
    if (pmly) {
        const float cc[5] = {C10, C11, 0.0f, C13, C14};
        float dps[4] = {0.f, 0.f, 0.f, 0.f};
        float psn2[4];
        #pragma unroll
        for (int k = 0; k < 5; k++) {
            int jy = y - 2 + k;
            bool ok = (unsigned)jy < (unsigned)NN;
            float aj = ok ? g_a[jy] : 0.0f;
            float bj = ok ? g_b[jy] : 0.0f;
            float pq[4];
            ld4z(pq, py_o + bi + (k-2)*SX, ok);
            const float* rk = rc + (k-2)*TSX;
            #pragma unroll
            for (int j = 0; j < 4; j++) {
                float dw = INVH*(C10*rk[j-2*TSX] + C11*rk[j-TSX] + C13*rk[j+TSX] + C14*rk[j+2*TSX]);
                float p = aj*pq[j] + bj*dw;
                if (k == 2) psn2[j] = p;
                else        dps[j] += cc[k]*p;
            }
        }
        float zq[4];
        ld4(zq, zy + bi);
        float ay = g_a[y], by = g_b[y];
        #pragma unroll
        for (int j = 0; j < 4; j++) {
            float dpsiy = INVH*dps[j];
            float z = ay*zq[j] + by*(d2y[j] + dpsiy);
            lap[j] += dpsiy + z;
            zq[j] = z;
        }
        st4(py_n + bi, psn2);
        st4(zy + bi, zq);
    }
    if (pmlx) {
        float pxv[12];
        ld4(pxv,   px_o + bi - 4);
        ld4(pxv+4, px_o + bi);
        ld4(pxv+8, px_o + bi + 4);
        float pm[8];   // psi_new at x positions x0-2 .. x0+5
        #pragma unroll
        for (int m = 0; m < 8; m++) {
            int pos = x0 + m - 2;
            int lc  = m - 2;          // offset from x0 in smem row
            pm[m] = 0.0f;
            if ((unsigned)pos < (unsigned)NN) {
                float dw = INVH*(C10*rc[lc-2] + C11*rc[lc-1] + C13*rc[lc+1] + C14*rc[lc+2]);
                pm[m] = g_a[pos]*pxv[m+2] + g_b[pos]*dw;
            }
        }
        float zq[4], pnew[4];
        ld4(zq, zx + bi);
        #pragma unroll
        for (int j = 0; j < 4; j++) {
            float dpsix = INVH*(C10*pm[j] + C11*pm[j+1] + C13*pm[j+3] + C14*pm[j+4]);
            float z = g_a[x0+j]*zq[j] + g_b[x0+j]*(d2x[j] + dpsix);
            lap[j] += dpsix + z;
            zq[j] = z;
            pnew[j] = pm[j+2];
        }
        st4(px_n + bi, pnew);
        st4(zx + bi, zq);
    }
}

__global__ void __launch_bounds__(256, 4) step_kernel(
    const int* __restrict__ rloc, const int* __restrict__ brloc,
    float* __restrict__ out, int t)
{
    __shared__ float s_wb[TROWS*TSX];
    __shared__ float s_ws[TROWS*TSX];

    const int p = t & 1, q = p ^ 1;
    float* base = g_state + PADC;
    const float* wc    = base + p*FIELD;        float* wn    = base + q*FIELD;
    const float* wcs   = base + (2+p)*FIELD;    float* wns   = base + (2+q)*FIELD;
    const float* pyb_o = base + (4+p)*FIELD;    float* pyb_n = base + (4+q)*FIELD;
    const float* pxb_o = base + (6+p)*FIELD;    float* pxb_n = base + (6+q)*FIELD;
    const float* pys_o = base + (8+p)*FIELD;    float* pys_n = base + (8+q)*FIELD;
    const float* pxs_o = base + (10+p)*FIELD;   float* pxs_n = base + (10+q)*FIELD;
    float* zyb = base + 12*FIELD;  float* zxb = base + 13*FIELD;
    float* zys = base + 14*FIELD;  float* zxs = base + 15*FIELD;

    const int s = blockIdx.z;
    const int sy = g_sloc[s*2], sxp = g_sloc[s*2+1];
    const int tx = threadIdx.x, ty = threadIdx.y;
    const int tid = ty*32 + tx;

    // Fused receiver recording of step t-1 (block (0,0,s) always runs)
    if (t > 0 && blockIdx.x == 0 && blockIdx.y == 0) {
        if (tid < NRECV) {
            int k = s*NRECV + tid;
            int ry = brloc[k*2] + 22, rx = brloc[k*2+1] + 22;
            out[OUT_RECBG + k*NT + (t-1)] = __ldg(wc + s*FS + ry*SX + rx);
        } else if (tid < 2*NRECV) {
            int k = s*NRECV + (tid - NRECV);
            int ry = rloc[k*2] + 22, rx = rloc[k*2+1] + 22;
            out[OUT_RECSC + k*NT + (t-1)] = __ldg(wcs + s*FS + ry*SX + rx);
        }
    }

    // Exact domain-of-dependence prune (uniform; before any sync)
    const int R = 4*(t+1);
    if (R < NN) {
        int by0 = blockIdx.y*8, bx0 = blockIdx.x*128;
        if (by0 > sy+R || by0+7 < sy-R || bx0 > sxp+R || bx0+127 < sxp-R) return;
    }

    // Cooperative smem load: both fields, 16 rows x 34 float4s each.
    {
        const int xbase = blockIdx.x*128 - 4;   // global x of local col 0 (4-aligned)
        const int ybase = blockIdx.y*8 - 4;     // global y of local row 0
        #pragma unroll
        for (int i = tid; i < 2*TROWS*34; i += 256) {
            int f   = (i >= TROWS*34);
            int rem = f ? i - TROWS*34 : i;
            int rr  = rem / 34;
            int c4  = rem % 34;
            int yg  = ybase + rr;
            float4 val = make_float4(0.f, 0.f, 0.f, 0.f);
            if ((unsigned)yg < (unsigned)NN) {
                const float* src = (f ? wcs : wc) + s*FS + yg*SX + xbase + c4*4;
                val = __ldg(reinterpret_cast<const float4*>(src));
            }
            float* dst = (f ? s_ws : s_wb) + rr*TSX + c4*4;
            *reinterpret_cast<float4*>(dst) = val;
        }
    }
    __syncthreads();

    const int qx = blockIdx.x*32 + tx;      // quad column 0..127
    const int y  = blockIdx.y*8 + ty;
    if (qx > 110 || y >= NN) return;
    const int x0 = qx * 4;
    if (R < NN) {
        if (y > sy+R || y < sy-R || x0 > sxp+R || x0+3 < sxp-R) return;
    }
    const int bi = s*FS + y*SX + x0;
    const bool pmly = (y  < 24) || (y  >= 420);
    const bool pmlx = (x0 < 24) || (x0 >= 420);
    const int r = ty + 4;         // local smem row of y
    const int c = tx*4 + 4;       // local smem col of x0

    // background field first (fully retired to release registers)
    float lap[4];
    {
        lap_field4s(s_wb, r, c, pyb_o, pyb_n, pxb_o, pxb_n, zyb, zxb,
                    bi, y, x0, pmly, pmlx, lap);
        float v2q[4], wpo[4], newv[4];
        ld4(v2q, g_v2dt2 + y*SX + x0);
        ld4(wpo, wn + bi);
        const float* rc = s_wb + r*TSX + c;
        #pragma unroll
        for (int j = 0; j < 4; j++)
            newv[j] = v2q[j]*lap[j] + 2.0f*rc[j] - wpo[j];
        if (y == sy && x0 == (sxp & ~3))
            newv[sxp & 3] += g_fbg[s*NT + t];
        st4(wn + bi, newv);
    }

    // scattered field (needs lap[] for the Born term)
    {
        float laps[4];
        lap_field4s(s_ws, r, c, pys_o, pys_n, pxs_o, pxs_n, zys, zxs,
                    bi, y, x0, pmly, pmlx, laps);
        float v2q[4], bornq[4], wpos[4], news[4];
        ld4(v2q,   g_v2dt2 + y*SX + x0);
        ld4(bornq, g_born  + y*SX + x0);
        ld4(wpos,  wns + bi);
        const float* rc = s_ws + r*TSX + c;
        #pragma unroll
        for (int j = 0; j < 4; j++)
            news[j] = v2q[j]*laps[j] + 2.0f*rc[j] - wpos[j] + bornq[j]*lap[j];
        if (y == sy && x0 == (sxp & ~3))
            news[sxp & 3] += g_fsc[s*NT + t];
        st4(wns + bi, news);
    }
}

__global__ void final_kernel(const int* __restrict__ rloc, const int* __restrict__ brloc,
                             float* __restrict__ out)
{
    const float* wb = g_state + PADC + 0*FIELD;
    const float* ws = g_state + PADC + 2*FIELD;
    int idx = blockIdx.x*blockDim.x + threadIdx.x;
    const int tot = NSHOT*444*444;
    if (idx < tot) {
        int s = idx / (444*444);
        int r = idx % (444*444);
        int y = r / 444, x = r % 444;
        out[idx]          = wb[s*FS + y*SX + x];
        out[OUT_SC + idx] = ws[s*FS + y*SX + x];
    }
    if (idx < 2*NSHOT*NRECV) {
        int which = idx / (NSHOT*NRECV);
        int k     = idx % (NSHOT*NRECV);
        int s = k / NRECV;
        if (which == 0) {
            int ry = brloc[k*2] + 22, rx = brloc[k*2+1] + 22;
            out[OUT_RECBG + k*NT + (NT-1)] = wb[s*FS + ry*SX + rx];
        } else {
            int ry = rloc[k*2] + 22, rx = rloc[k*2+1] + 22;
            out[OUT_RECSC + k*NT + (NT-1)] = ws[s*FS + ry*SX + rx];
        }
    }
}

extern "C" void kernel_launch(void* const* d_in, const int* in_sizes, int n_in,
                              void* d_out, int out_size) {
    const float* v     = (const float*)d_in[0];
    const float* sc    = (const float*)d_in[1];
    const float* amp   = (const float*)d_in[2];
    const int*   sloc  = (const int*)  d_in[3];
    const int*   rloc  = (const int*)  d_in[4];
    const int*   brloc = (const int*)  d_in[5];
    float* out = (float*)d_out;

    zero_kernel<<<2048, 256>>>();
    {
        dim3 b(64, 1), g(7, 444);
        init_kernel<<<g, b>>>(v, sc, amp, sloc);
    }
    {
        dim3 b(32, 8), g(4, 56, NSHOT);   // constant grid every step (proven critical)
        for (int t = 0; t < NT; t++)
            step_kernel<<<g, b>>>(rloc, brloc, out, t);
    }
    final_kernel<<<(NSHOT*444*444 + 255)/256, 256>>>(rloc, brloc, out);
}

// round 14
// speedup vs baseline: 1.0386x; 1.0386x over previous
#include <cuda_runtime.h>
#include <math.h>

// Problem constants
#define NSHOT 4
#define NT    300
#define NRECV 100
#define NN    444          // padded grid (400 + 2*22)
#define SX    448          // row stride (zero pad cols 444..447)
#define FS    (NN*SX)      // per-shot plane: 198,912 floats
#define FIELD (NSHOT*FS)   // per field: 795,648 floats
#define PADC  16           // head pad floats (zero) before field 0
#define DTF   0.0005f
#define INVH  0.2f
#define INVH2 0.04f
#define C10 (1.0f/12.0f)
#define C11 (-2.0f/3.0f)
#define C13 (2.0f/3.0f)
#define C14 (-1.0f/12.0f)
#define C20 (-1.0f/12.0f)
#define C21 (4.0f/3.0f)
#define C22 (-2.5f)
#define OUT_SC    (NSHOT*444*444)
#define OUT_RECBG (2*NSHOT*444*444)
#define OUT_RECSC (OUT_RECBG + NSHOT*NRECV*NT)
#define SIGMA_MAX 259.0408229618301f
#define ALPHA_F   78.53981633974483f

// 16 state fields, contiguous:
// 0:WBG0 1:WBG1 2:WSC0 3:WSC1 4:PYB0 5:PYB1 6:PXB0 7:PXB1
// 8:PYS0 9:PYS1 10:PXS0 11:PXS1 12:ZYB 13:ZXB 14:ZYS 15:ZXS
__device__ __align__(256) float g_state[16*FIELD + 2*PADC];
__device__ __align__(256) float g_v2dt2[FS];
__device__ __align__(256) float g_born[FS];
__device__ float g_a[SX];
__device__ float g_b[SX];
__device__ float g_fbg[NSHOT*NT];
__device__ float g_fsc[NSHOT*NT];
__device__ int   g_sloc[NSHOT*2];

__global__ void zero_kernel() {
    const int n = 16*FIELD + 2*PADC;
    for (int i = blockIdx.x*blockDim.x + threadIdx.x; i < n; i += gridDim.x*blockDim.x)
        g_state[i] = 0.0f;
}

__global__ void init_kernel(const float* __restrict__ v, const float* __restrict__ sc,
                            const float* __restrict__ amp, const int* __restrict__ sloc) {
    int x = blockIdx.x*blockDim.x + threadIdx.x;   // 0..447
    int y = blockIdx.y;                            // 0..443
    if (x < NN) {
        int vy = min(max(y-22, 0), 399);
        int vx = min(max(x-22, 0), 399);
        float vv = v[vy*400 + vx];
        float ss = (y >= 22 && y < 422 && x >= 22 && x < 422) ? sc[(y-22)*400 + (x-22)] : 0.0f;
        g_v2dt2[y*SX+x] = (vv*DTF)*(vv*DTF);
        g_born [y*SX+x] = 2.0f*vv*ss*DTF*DTF;
    } else if (y < NN) {
        g_v2dt2[y*SX+x] = 0.0f;
        g_born [y*SX+x] = 0.0f;
    }
    if (y == 0) {
        float a = 0.0f, b = 0.0f;
        if (x < NN) {
            float fi = (float)x;
            float f1 = fminf(fmaxf((22.0f - fi)/20.0f, 0.0f), 1.0f);
            float f2 = fminf(fmaxf((fi - 421.0f)/20.0f, 0.0f), 1.0f);
            float frac = fmaxf(f1, f2);
            float sigma = SIGMA_MAX * frac * frac;
            a = expf(-(sigma + ALPHA_F)*DTF);
            b = (sigma > 0.0f) ? sigma/(sigma + ALPHA_F)*(a - 1.0f) : 0.0f;
        }
        g_a[x] = a; g_b[x] = b;
    }
    int lid = y*SX + x;
    if (lid < NSHOT*NT) {
        int s = lid / NT, t = lid % NT;
        int ly = sloc[s*2+0], lx = sloc[s*2+1];
        float vv = v [ly*400 + lx];
        float ss = sc[ly*400 + lx];
        float a  = amp[s*NT + t];
        g_fbg[lid] = (-a * (vv*vv)) * DTF * DTF;
        g_fsc[lid] = ((-2.0f * a) * (vv*ss)) * DTF * DTF;
    }
    if (lid < NSHOT*2) g_sloc[lid] = sloc[lid] + 22;
}

__device__ __forceinline__ void ld4(float* d, const float* p) {
    float4 t = __ldg(reinterpret_cast<const float4*>(p));
    d[0]=t.x; d[1]=t.y; d[2]=t.z; d[3]=t.w;
}
__device__ __forceinline__ void ld4z(float* d, const float* p, bool pred) {
    if (pred) ld4(d, p);
    else { d[0]=0.f; d[1]=0.f; d[2]=0.f; d[3]=0.f; }
}
__device__ __forceinline__ void st4(float* p, const float* d) {
    float4 t; t.x=d[0]; t.y=d[1]; t.z=d[2]; t.w=d[3];
    *reinterpret_cast<float4*>(p) = t;
}

// PML-Laplacian for a quad of 4 x-points of one field. wx[12] = w over x0-4..x0+7.
__device__ __forceinline__ void lap_field4(
    const float* __restrict__ w,
    const float* __restrict__ py_o, float* __restrict__ py_n,
    const float* __restrict__ px_o, float* __restrict__ px_n,
    float* __restrict__ zy, float* __restrict__ zx,
    int bi, int y, int x0, bool pmly, bool pmlx,
    const float* wx, float lap[4])
{
    float ym1[4], ym2[4], yp1[4], yp2[4];
    ld4z(ym1, w + bi - SX,   y >= 1);
    ld4z(ym2, w + bi - 2*SX, y >= 2);
    ld4z(yp1, w + bi + SX,   y < NN-1);
    ld4z(yp2, w + bi + 2*SX, y < NN-2);
    float d2y[4], d2x[4];
    #pragma unroll
    for (int j = 0; j < 4; j++) {
        d2y[j] = INVH2*(C20*(ym2[j]+yp2[j]) + C21*(ym1[j]+yp1[j]) + C22*wx[4+j]);
        d2x[j] = INVH2*(C20*(wx[2+j]+wx[6+j]) + C21*(wx[3+j]+wx[5+j]) + C22*wx[4+j]);
        lap[j] = d2y[j] + d2x[j];
    }
    if (pmly) {
        float ym3[4], ym4[4], yp3[4], yp4[4];
        ld4z(ym3, w + bi - 3*SX, y >= 3);
        ld4z(ym4, w + bi - 4*SX, y >= 4);
        ld4z(yp3, w + bi + 3*SX, y < NN-3);
        ld4z(yp4, w + bi + 4*SX, y < NN-4);
        const float* wrow[9] = {ym4, ym3, ym2, ym1, wx+4, yp1, yp2, yp3, yp4};
        const float cc[5] = {C10, C11, 0.0f, C13, C14};
        float dps[4] = {0.f, 0.f, 0.f, 0.f};
        float psn2[4];
        #pragma unroll
        for (int k = 0; k < 5; k++) {
            int jy = y - 2 + k;
            bool ok = (unsigned)jy < (unsigned)NN;
            float aj = ok ? g_a[jy] : 0.0f;
            float bj = ok ? g_b[jy] : 0.0f;
            float pq[4];
            ld4z(pq, py_o + bi + (k-2)*SX, ok);
            #pragma unroll
            for (int j = 0; j < 4; j++) {
                float dw = INVH*(C10*wrow[k][j] + C11*wrow[k+1][j] + C13*wrow[k+3][j] + C14*wrow[k+4][j]);
                float p = aj*pq[j] + bj*dw;
                if (k == 2) psn2[j] = p;
                else        dps[j] += cc[k]*p;
            }
        }
        float zq[4];
        ld4(zq, zy + bi);
        float ay = g_a[y], by = g_b[y];
        #pragma unroll
        for (int j = 0; j < 4; j++) {
            float dpsiy = INVH*dps[j];
            float z = ay*zq[j] + by*(d2y[j] + dpsiy);
            lap[j] += dpsiy + z;
            zq[j] = z;
        }
        st4(py_n + bi, psn2);
        st4(zy + bi, zq);
    }
    if (pmlx) {
        float pxv[12];
        ld4(pxv,   px_o + bi - 4);
        ld4(pxv+4, px_o + bi);
        ld4(pxv+8, px_o + bi + 4);
        float pm[8];   // psi_new at x positions x0-2 .. x0+5
        #pragma unroll
        for (int m = 0; m < 8; m++) {
            int pos = x0 + m - 2;
            int idx = m + 2;          // index into 12-wide local windows
            pm[m] = 0.0f;
            if ((unsigned)pos < (unsigned)NN) {
                float dw = INVH*(C10*wx[idx-2] + C11*wx[idx-1] + C13*wx[idx+1] + C14*wx[idx+2]);
                pm[m] = g_a[pos]*pxv[idx] + g_b[pos]*dw;
            }
        }
        float zq[4], pnew[4];
        ld4(zq, zx + bi);
        #pragma unroll
        for (int j = 0; j < 4; j++) {
            float dpsix = INVH*(C10*pm[j] + C11*pm[j+1] + C13*pm[j+3] + C14*pm[j+4]);
            float z = g_a[x0+j]*zq[j] + g_b[x0+j]*(d2x[j] + dpsix);
            lap[j] += dpsix + z;
            zq[j] = z;
            pnew[j] = pm[j+2];
        }
        st4(px_n + bi, pnew);
        st4(zx + bi, zq);
    }
}

__global__ void __launch_bounds__(256, 4) step_kernel(
    const int* __restrict__ rloc, const int* __restrict__ brloc,
    float* __restrict__ out, int t)
{
    const int p = t & 1, q = p ^ 1;
    float* base = g_state + PADC;
    const float* wc    = base + p*FIELD;        float* wn    = base + q*FIELD;
    const float* wcs   = base + (2+p)*FIELD;    float* wns   = base + (2+q)*FIELD;
    const float* pyb_o = base + (4+p)*FIELD;    float* pyb_n = base + (4+q)*FIELD;
    const float* pxb_o = base + (6+p)*FIELD;    float* pxb_n = base + (6+q)*FIELD;
    const float* pys_o = base + (8+p)*FIELD;    float* pys_n = base + (8+q)*FIELD;
    const float* pxs_o = base + (10+p)*FIELD;   float* pxs_n = base + (10+q)*FIELD;
    float* zyb = base + 12*FIELD;  float* zxb = base + 13*FIELD;
    float* zys = base + 14*FIELD;  float* zxs = base + 15*FIELD;

    const int s = blockIdx.z;
    const int sy = g_sloc[s*2], sxp = g_sloc[s*2+1];

    // Fused receiver recording of step t-1 (before any early exit)
    if (t > 0 && blockIdx.x == 0 && blockIdx.y == 0) {
        int tid = threadIdx.y*blockDim.x + threadIdx.x;
        if (tid < NRECV) {
            int k = s*NRECV + tid;
            int ry = brloc[k*2] + 22, rx = brloc[k*2+1] + 22;
            out[OUT_RECBG + k*NT + (t-1)] = __ldg(wc + s*FS + ry*SX + rx);
        } else if (tid < 2*NRECV) {
            int k = s*NRECV + (tid - NRECV);
            int ry = rloc[k*2] + 22, rx = rloc[k*2+1] + 22;
            out[OUT_RECSC + k*NT + (t-1)] = __ldg(wcs + s*FS + ry*SX + rx);
        }
    }

    // Heavy-tiles-first dispatch permutation: PML-containing tiles (y tiles
    // 0-2 and 53-55, x tiles 0 and 3) map to the LOWEST block indices so the
    // slow tiles start in wave 1 and cheap interior tiles pack the tail.
    // Pure bijections; math unchanged.
    const int ybRaw = blockIdx.y;
    const int yblk  = (ybRaw < 3) ? ybRaw : ((ybRaw < 6) ? ybRaw + 50 : ybRaw - 3);
    const int xmap[4] = {0, 3, 1, 2};
    const int xblk  = xmap[blockIdx.x];

    // Exact domain-of-dependence box: outside source +- 4(t+1), all state is
    // exactly zero at this step (stencil reach = 4 cells/axis/step), so skip.
    const int R = 4*(t+1);
    if (R < NN) {
        int by0 = yblk*8, bx0 = xblk*128;
        if (by0 > sy+R || by0+7 < sy-R || bx0 > sxp+R || bx0+127 < sxp-R) return;
    }

    const int qx = xblk*32 + threadIdx.x;   // quad column 0..127
    const int y  = yblk*8  + threadIdx.y;
    if (qx > 110 || y >= NN) return;
    const int x0 = qx * 4;
    if (R < NN) {
        if (y > sy+R || y < sy-R || x0 > sxp+R || x0+3 < sxp-R) return;
    }
    const int bi = s*FS + y*SX + x0;
    const bool pmly = (y  < 24) || (y  >= 420);
    const bool pmlx = (x0 < 24) || (x0 >= 420);

    // background field first (fully retired to release registers)
    float lap[4];
    {
        float wxb[12];
        ld4(wxb,   wc + bi - 4);
        ld4(wxb+4, wc + bi);
        ld4(wxb+8, wc + bi + 4);
        lap_field4(wc, pyb_o, pyb_n, pxb_o, pxb_n, zyb, zxb, bi, y, x0, pmly, pmlx, wxb, lap);
        float v2q[4], wpo[4], newv[4];
        ld4(v2q, g_v2dt2 + y*SX + x0);
        ld4(wpo, wn + bi);
        #pragma unroll
        for (int j = 0; j < 4; j++)
            newv[j] = v2q[j]*lap[j] + 2.0f*wxb[4+j] - wpo[j];
        if (y == sy && x0 == (sxp & ~3))
            newv[sxp & 3] += g_fbg[s*NT + t];
        st4(wn + bi, newv);
    }

    // scattered field (needs lap[] for the Born term)
    {
        float wxs[12];
        ld4(wxs,   wcs + bi - 4);
        ld4(wxs+4, wcs + bi);
        ld4(wxs+8, wcs + bi + 4);
        float laps[4];
        lap_field4(wcs, pys_o, pys_n, pxs_o, pxs_n, zys, zxs, bi, y, x0, pmly, pmlx, wxs, laps);
        float v2q[4], bornq[4], wpos[4], news[4];
        ld4(v2q,   g_v2dt2 + y*SX + x0);
        ld4(bornq, g_born  + y*SX + x0);
        ld4(wpos,  wns + bi);
        #pragma unroll
        for (int j = 0; j < 4; j++)
            news[j] = v2q[j]*laps[j] + 2.0f*wxs[4+j] - wpos[j] + bornq[j]*lap[j];
        if (y == sy && x0 == (sxp & ~3))
            news[sxp & 3] += g_fsc[s*NT + t];
        st4(wns + bi, news);
    }
}

__global__ void final_kernel(const int* __restrict__ rloc, const int* __restrict__ brloc,
                             float* __restrict__ out)
{
    const float* wb = g_state + PADC + 0*FIELD;
    const float* ws = g_state + PADC + 2*FIELD;
    int idx = blockIdx.x*blockDim.x + threadIdx.x;
    const int tot = NSHOT*444*444;
    if (idx < tot) {
        int s = idx / (444*444);
        int r = idx % (444*444);
        int y = r / 444, x = r % 444;
        out[idx]          = wb[s*FS + y*SX + x];
        out[OUT_SC + idx] = ws[s*FS + y*SX + x];
    }
    if (idx < 2*NSHOT*NRECV) {
        int which = idx / (NSHOT*NRECV);
        int k     = idx % (NSHOT*NRECV);
        int s = k / NRECV;
        if (which == 0) {
            int ry = brloc[k*2] + 22, rx = brloc[k*2+1] + 22;
            out[OUT_RECBG + k*NT + (NT-1)] = wb[s*FS + ry*SX + rx];
        } else {
            int ry = rloc[k*2] + 22, rx = rloc[k*2+1] + 22;
            out[OUT_RECSC + k*NT + (NT-1)] = ws[s*FS + ry*SX + rx];
        }
    }
}

extern "C" void kernel_launch(void* const* d_in, const int* in_sizes, int n_in,
                              void* d_out, int out_size) {
    const float* v     = (const float*)d_in[0];
    const float* sc    = (const float*)d_in[1];
    const float* amp   = (const float*)d_in[2];
    const int*   sloc  = (const int*)  d_in[3];
    const int*   rloc  = (const int*)  d_in[4];
    const int*   brloc = (const int*)  d_in[5];
    float* out = (float*)d_out;

    zero_kernel<<<2048, 256>>>();
    {
        dim3 b(64, 1), g(7, 444);
        init_kernel<<<g, b>>>(v, sc, amp, sloc);
    }
    {
        dim3 b(32, 8), g(4, 56, NSHOT);   // constant grid every step (proven critical)
        for (int t = 0; t < NT; t++)
            step_kernel<<<g, b>>>(rloc, brloc, out, t);
    }
    final_kernel<<<(NSHOT*444*444 + 255)/256, 256>>>(rloc, brloc, out);
}

// round 15
// speedup vs baseline: 1.1218x; 1.0800x over previous
#include <cuda_runtime.h>
#include <math.h>

// Problem constants
#define NSHOT 4
#define NT    300
#define NRECV 100
#define NN    444          // padded grid (400 + 2*22)
#define SX    448          // row stride (zero pad cols 444..447)
#define FS    (NN*SX)      // per-shot plane: 198,912 floats
#define FIELD (NSHOT*FS)   // per field: 795,648 floats
#define PADC  16           // head pad floats (zero) before field 0
#define DTF   0.0005f
#define INVH  0.2f
#define INVH2 0.04f
#define C10 (1.0f/12.0f)
#define C11 (-2.0f/3.0f)
#define C13 (2.0f/3.0f)
#define C14 (-1.0f/12.0f)
#define C20 (-1.0f/12.0f)
#define C21 (4.0f/3.0f)
#define C22 (-2.5f)
#define OUT_SC    (NSHOT*444*444)
#define OUT_RECBG (2*NSHOT*444*444)
#define OUT_RECSC (OUT_RECBG + NSHOT*NRECV*NT)
#define SIGMA_MAX 259.0408229618301f
#define ALPHA_F   78.53981633974483f

// 16 state fields, contiguous:
// 0:WBG0 1:WBG1 2:WSC0 3:WSC1 4:PYB0 5:PYB1 6:PXB0 7:PXB1
// 8:PYS0 9:PYS1 10:PXS0 11:PXS1 12:ZYB 13:ZXB 14:ZYS 15:ZXS
__device__ __align__(256) float g_state[16*FIELD + 2*PADC];
__device__ __align__(256) float g_v2dt2[FS];
__device__ __align__(256) float g_born[FS];
__device__ float g_a[SX];
__device__ float g_b[SX];
__device__ float g_fbg[NSHOT*NT];
__device__ float g_fsc[NSHOT*NT];
__device__ int   g_sloc[NSHOT*2];

__global__ void zero_kernel() {
    const int n = 16*FIELD + 2*PADC;
    for (int i = blockIdx.x*blockDim.x + threadIdx.x; i < n; i += gridDim.x*blockDim.x)
        g_state[i] = 0.0f;
}

__global__ void init_kernel(const float* __restrict__ v, const float* __restrict__ sc,
                            const float* __restrict__ amp, const int* __restrict__ sloc) {
    int x = blockIdx.x*blockDim.x + threadIdx.x;   // 0..447
    int y = blockIdx.y;                            // 0..443
    if (x < NN) {
        int vy = min(max(y-22, 0), 399);
        int vx = min(max(x-22, 0), 399);
        float vv = v[vy*400 + vx];
        float ss = (y >= 22 && y < 422 && x >= 22 && x < 422) ? sc[(y-22)*400 + (x-22)] : 0.0f;
        g_v2dt2[y*SX+x] = (vv*DTF)*(vv*DTF);
        g_born [y*SX+x] = 2.0f*vv*ss*DTF*DTF;
    } else if (y < NN) {
        g_v2dt2[y*SX+x] = 0.0f;
        g_born [y*SX+x] = 0.0f;
    }
    if (y == 0) {
        float a = 0.0f, b = 0.0f;
        if (x < NN) {
            float fi = (float)x;
            float f1 = fminf(fmaxf((22.0f - fi)/20.0f, 0.0f), 1.0f);
            float f2 = fminf(fmaxf((fi - 421.0f)/20.0f, 0.0f), 1.0f);
            float frac = fmaxf(f1, f2);
            float sigma = SIGMA_MAX * frac * frac;
            a = expf(-(sigma + ALPHA_F)*DTF);
            b = (sigma > 0.0f) ? sigma/(sigma + ALPHA_F)*(a - 1.0f) : 0.0f;
        }
        g_a[x] = a; g_b[x] = b;
    }
    int lid = y*SX + x;
    if (lid < NSHOT*NT) {
        int s = lid / NT, t = lid % NT;
        int ly = sloc[s*2+0], lx = sloc[s*2+1];
        float vv = v [ly*400 + lx];
        float ss = sc[ly*400 + lx];
        float a  = amp[s*NT + t];
        g_fbg[lid] = (-a * (vv*vv)) * DTF * DTF;
        g_fsc[lid] = ((-2.0f * a) * (vv*ss)) * DTF * DTF;
    }
    if (lid < NSHOT*2) g_sloc[lid] = sloc[lid] + 22;
}

__device__ __forceinline__ void ld4(float* d, const float* p) {
    float4 t = __ldg(reinterpret_cast<const float4*>(p));
    d[0]=t.x; d[1]=t.y; d[2]=t.z; d[3]=t.w;
}
__device__ __forceinline__ void ld4z(float* d, const float* p, bool pred) {
    if (pred) ld4(d, p);
    else { d[0]=0.f; d[1]=0.f; d[2]=0.f; d[3]=0.f; }
}
__device__ __forceinline__ void st4(float* p, const float* d) {
    float4 t; t.x=d[0]; t.y=d[1]; t.z=d[2]; t.w=d[3];
    *reinterpret_cast<float4*>(p) = t;
}

// PML-Laplacian for a quad of 4 x-points of one field. wx[12] = w over x0-4..x0+7.
__device__ __forceinline__ void lap_field4(
    const float* __restrict__ w,
    const float* __restrict__ py_o, float* __restrict__ py_n,
    const float* __restrict__ px_o, float* __restrict__ px_n,
    float* __restrict__ zy, float* __restrict__ zx,
    int bi, int y, int x0, bool pmly, bool pmlx,
    const float* wx, float lap[4])
{
    float ym1[4], ym2[4], yp1[4], yp2[4];
    ld4z(ym1, w + bi - SX,   y >= 1);
    ld4z(ym2, w + bi - 2*SX, y >= 2);
    ld4z(yp1, w + bi + SX,   y < NN-1);
    ld4z(yp2, w + bi + 2*SX, y < NN-2);
    float d2y[4], d2x[4];
    #pragma unroll
    for (int j = 0; j < 4; j++) {
        d2y[j] = INVH2*(C20*(ym2[j]+yp2[j]) + C21*(ym1[j]+yp1[j]) + C22*wx[4+j]);
        d2x[j] = INVH2*(C20*(wx[2+j]+wx[6+j]) + C21*(wx[3+j]+wx[5+j]) + C22*wx[4+j]);
        lap[j] = d2y[j] + d2x[j];
    }
    if (pmly) {
        float ym3[4], ym4[4], yp3[4], yp4[4];
        ld4z(ym3, w + bi - 3*SX, y >= 3);
        ld4z(ym4, w + bi - 4*SX, y >= 4);
        ld4z(yp3, w + bi + 3*SX, y < NN-3);
        ld4z(yp4, w + bi + 4*SX, y < NN-4);
        const float* wrow[9] = {ym4, ym3, ym2, ym1, wx+4, yp1, yp2, yp3, yp4};
        const float cc[5] = {C10, C11, 0.0f, C13, C14};
        float dps[4] = {0.f, 0.f, 0.f, 0.f};
        float psn2[4];
        #pragma unroll
        for (int k = 0; k < 5; k++) {
            int jy = y - 2 + k;
            bool ok = (unsigned)jy < (unsigned)NN;
            float aj = ok ? g_a[jy] : 0.0f;
            float bj = ok ? g_b[jy] : 0.0f;
            float pq[4];
            ld4z(pq, py_o + bi + (k-2)*SX, ok);
            #pragma unroll
            for (int j = 0; j < 4; j++) {
                float dw = INVH*(C10*wrow[k][j] + C11*wrow[k+1][j] + C13*wrow[k+3][j] + C14*wrow[k+4][j]);
                float p = aj*pq[j] + bj*dw;
                if (k == 2) psn2[j] = p;
                else        dps[j] += cc[k]*p;
            }
        }
        float zq[4];
        ld4(zq, zy + bi);
        float ay = g_a[y], by = g_b[y];
        #pragma unroll
        for (int j = 0; j < 4; j++) {
            float dpsiy = INVH*dps[j];
            float z = ay*zq[j] + by*(d2y[j] + dpsiy);
            lap[j] += dpsiy + z;
            zq[j] = z;
        }
        st4(py_n + bi, psn2);
        st4(zy + bi, zq);
    }
    if (pmlx) {
        float pxv[12];
        ld4(pxv,   px_o + bi - 4);
        ld4(pxv+4, px_o + bi);
        ld4(pxv+8, px_o + bi + 4);
        float pm[8];   // psi_new at x positions x0-2 .. x0+5
        #pragma unroll
        for (int m = 0; m < 8; m++) {
            int pos = x0 + m - 2;
            int idx = m + 2;          // index into 12-wide local windows
            pm[m] = 0.0f;
            if ((unsigned)pos < (unsigned)NN) {
                float dw = INVH*(C10*wx[idx-2] + C11*wx[idx-1] + C13*wx[idx+1] + C14*wx[idx+2]);
                pm[m] = g_a[pos]*pxv[idx] + g_b[pos]*dw;
            }
        }
        float zq[4], pnew[4];
        ld4(zq, zx + bi);
        #pragma unroll
        for (int j = 0; j < 4; j++) {
            float dpsix = INVH*(C10*pm[j] + C11*pm[j+1] + C13*pm[j+3] + C14*pm[j+4]);
            float z = g_a[x0+j]*zq[j] + g_b[x0+j]*(d2x[j] + dpsix);
            lap[j] += dpsix + z;
            zq[j] = z;
            pnew[j] = pm[j+2];
        }
        st4(px_n + bi, pnew);
        st4(zx + bi, zq);
    }
}

__global__ void __launch_bounds__(256, 4) step_kernel(
    const int* __restrict__ rloc, const int* __restrict__ brloc,
    float* __restrict__ out, int t)
{
    // PDL: this launch may begin while the previous step is still draining.
    // Block here until the predecessor's writes are complete/visible, then
    // proceed. Must precede ANY global read.
    cudaGridDependencySynchronize();

    const int p = t & 1, q = p ^ 1;
    float* base = g_state + PADC;
    const float* wc    = base + p*FIELD;        float* wn    = base + q*FIELD;
    const float* wcs   = base + (2+p)*FIELD;    float* wns   = base + (2+q)*FIELD;
    const float* pyb_o = base + (4+p)*FIELD;    float* pyb_n = base + (4+q)*FIELD;
    const float* pxb_o = base + (6+p)*FIELD;    float* pxb_n = base + (6+q)*FIELD;
    const float* pys_o = base + (8+p)*FIELD;    float* pys_n = base + (8+q)*FIELD;
    const float* pxs_o = base + (10+p)*FIELD;   float* pxs_n = base + (10+q)*FIELD;
    float* zyb = base + 12*FIELD;  float* zxb = base + 13*FIELD;
    float* zys = base + 14*FIELD;  float* zxs = base + 15*FIELD;

    const int s = blockIdx.z;
    const int sy = g_sloc[s*2], sxp = g_sloc[s*2+1];

    // Fused receiver recording of step t-1 (before any early exit)
    if (t > 0 && blockIdx.x == 0 && blockIdx.y == 0) {
        int tid = threadIdx.y*blockDim.x + threadIdx.x;
        if (tid < NRECV) {
            int k = s*NRECV + tid;
            int ry = brloc[k*2] + 22, rx = brloc[k*2+1] + 22;
            out[OUT_RECBG + k*NT + (t-1)] = __ldg(wc + s*FS + ry*SX + rx);
        } else if (tid < 2*NRECV) {
            int k = s*NRECV + (tid - NRECV);
            int ry = rloc[k*2] + 22, rx = rloc[k*2+1] + 22;
            out[OUT_RECSC + k*NT + (t-1)] = __ldg(wcs + s*FS + ry*SX + rx);
        }
    }

    // Exact domain-of-dependence box: outside source +- 4(t+1), all state is
    // exactly zero at this step (stencil reach = 4 cells/axis/step), so skip.
    const int R = 4*(t+1);
    if (R < NN) {
        int by0 = blockIdx.y*8, bx0 = blockIdx.x*128;
        if (by0 > sy+R || by0+7 < sy-R || bx0 > sxp+R || bx0+127 < sxp-R) return;
    }

    const int qx = blockIdx.x*blockDim.x + threadIdx.x;   // quad column 0..127
    const int y  = blockIdx.y*blockDim.y + threadIdx.y;
    if (qx > 110 || y >= NN) return;
    const int x0 = qx * 4;
    if (R < NN) {
        if (y > sy+R || y < sy-R || x0 > sxp+R || x0+3 < sxp-R) return;
    }
    const int bi = s*FS + y*SX + x0;
    const bool pmly = (y  < 24) || (y  >= 420);
    const bool pmlx = (x0 < 24) || (x0 >= 420);

    // background field first (fully retired to release registers)
    float lap[4];
    {
        float wxb[12];
        ld4(wxb,   wc + bi - 4);
        ld4(wxb+4, wc + bi);
        ld4(wxb+8, wc + bi + 4);
        lap_field4(wc, pyb_o, pyb_n, pxb_o, pxb_n, zyb, zxb, bi, y, x0, pmly, pmlx, wxb, lap);
        float v2q[4], wpo[4], newv[4];
        ld4(v2q, g_v2dt2 + y*SX + x0);
        ld4(wpo, wn + bi);
        #pragma unroll
        for (int j = 0; j < 4; j++)
            newv[j] = v2q[j]*lap[j] + 2.0f*wxb[4+j] - wpo[j];
        if (y == sy && x0 == (sxp & ~3))
            newv[sxp & 3] += g_fbg[s*NT + t];
        st4(wn + bi, newv);
    }

    // scattered field (needs lap[] for the Born term)
    {
        float wxs[12];
        ld4(wxs,   wcs + bi - 4);
        ld4(wxs+4, wcs + bi);
        ld4(wxs+8, wcs + bi + 4);
        float laps[4];
        lap_field4(wcs, pys_o, pys_n, pxs_o, pxs_n, zys, zxs, bi, y, x0, pmly, pmlx, wxs, laps);
        float v2q[4], bornq[4], wpos[4], news[4];
        ld4(v2q,   g_v2dt2 + y*SX + x0);
        ld4(bornq, g_born  + y*SX + x0);
        ld4(wpos,  wns + bi);
        #pragma unroll
        for (int j = 0; j < 4; j++)
            news[j] = v2q[j]*laps[j] + 2.0f*wxs[4+j] - wpos[j] + bornq[j]*lap[j];
        if (y == sy && x0 == (sxp & ~3))
            news[sxp & 3] += g_fsc[s*NT + t];
        st4(wns + bi, news);
    }
}

__global__ void final_kernel(const int* __restrict__ rloc, const int* __restrict__ brloc,
                             float* __restrict__ out)
{
    cudaGridDependencySynchronize();   // PDL-chained after the last step

    const float* wb = g_state + PADC + 0*FIELD;
    const float* ws = g_state + PADC + 2*FIELD;
    int idx = blockIdx.x*blockDim.x + threadIdx.x;
    const int tot = NSHOT*444*444;
    if (idx < tot) {
        int s = idx / (444*444);
        int r = idx % (444*444);
        int y = r / 444, x = r % 444;
        out[idx]          = wb[s*FS + y*SX + x];
        out[OUT_SC + idx] = ws[s*FS + y*SX + x];
    }
    if (idx < 2*NSHOT*NRECV) {
        int which = idx / (NSHOT*NRECV);
        int k     = idx % (NSHOT*NRECV);
        int s = k / NRECV;
        if (which == 0) {
            int ry = brloc[k*2] + 22, rx = brloc[k*2+1] + 22;
            out[OUT_RECBG + k*NT + (NT-1)] = wb[s*FS + ry*SX + rx];
        } else {
            int ry = rloc[k*2] + 22, rx = rloc[k*2+1] + 22;
            out[OUT_RECSC + k*NT + (NT-1)] = ws[s*FS + ry*SX + rx];
        }
    }
}

extern "C" void kernel_launch(void* const* d_in, const int* in_sizes, int n_in,
                              void* d_out, int out_size) {
    const float* v     = (const float*)d_in[0];
    const float* sc    = (const float*)d_in[1];
    const float* amp   = (const float*)d_in[2];
    const int*   sloc  = (const int*)  d_in[3];
    const int*   rloc  = (const int*)  d_in[4];
    const int*   brloc = (const int*)  d_in[5];
    float* out = (float*)d_out;

    zero_kernel<<<2048, 256>>>();
    {
        dim3 b(64, 1), g(7, 444);
        init_kernel<<<g, b>>>(v, sc, amp, sloc);
    }
    {
        // PDL launches: each step may be dispatched while the previous one
        // drains; in-kernel cudaGridDependencySynchronize() enforces order.
        cudaLaunchAttribute attrs[1];
        attrs[0].id = cudaLaunchAttributeProgrammaticStreamSerialization;
        attrs[0].val.programmaticStreamSerializationAllowed = 1;

        cudaLaunchConfig_t cfg = {};
        cfg.gridDim  = dim3(4, 56, NSHOT);   // constant grid (proven critical)
        cfg.blockDim = dim3(32, 8);
        cfg.dynamicSmemBytes = 0;
        cfg.stream = 0;
        cfg.attrs = attrs;
        cfg.numAttrs = 1;

        for (int t = 0; t < NT; t++)
            cudaLaunchKernelEx(&cfg, step_kernel, rloc, brloc, out, t);

        cudaLaunchConfig_t cfgf = cfg;
        cfgf.gridDim  = dim3((NSHOT*444*444 + 255)/256, 1, 1);
        cfgf.blockDim = dim3(256, 1, 1);
        cudaLaunchKernelEx(&cfgf, final_kernel, rloc, brloc, out);
    }
}

// round 17
// speedup vs baseline: 1.1329x; 1.0100x over previous
#include <cuda_runtime.h>
#include <math.h>

// Problem constants
#define NSHOT 4
#define NT    300
#define NRECV 100
#define NN    444          // padded grid (400 + 2*22)
#define SX    448          // row stride (zero pad cols 444..447)
#define FS    (NN*SX)      // per-shot plane: 198,912 floats
#define FIELD (NSHOT*FS)   // per field: 795,648 floats
#define PADC  16           // head pad floats (zero) before field 0
#define DTF   0.0005f
#define INVH  0.2f
#define INVH2 0.04f
#define C10 (1.0f/12.0f)
#define C11 (-2.0f/3.0f)
#define C13 (2.0f/3.0f)
#define C14 (-1.0f/12.0f)
#define C20 (-1.0f/12.0f)
#define C21 (4.0f/3.0f)
#define C22 (-2.5f)
#define OUT_SC    (NSHOT*444*444)
#define OUT_RECBG (2*NSHOT*444*444)
#define OUT_RECSC (OUT_RECBG + NSHOT*NRECV*NT)
#define SIGMA_MAX 259.0408229618301f
#define ALPHA_F   78.53981633974483f
#define TPS 224            // tiles per shot: 56 yblk x 4 xblk

// 16 state fields, contiguous:
// 0:WBG0 1:WBG1 2:WSC0 3:WSC1 4:PYB0 5:PYB1 6:PXB0 7:PXB1
// 8:PYS0 9:PYS1 10:PXS0 11:PXS1 12:ZYB 13:ZXB 14:ZYS 15:ZXS
__device__ __align__(256) float g_state[16*FIELD + 2*PADC];
__device__ __align__(256) float g_v2dt2[FS];
__device__ __align__(256) float g_born[FS];
__device__ float g_a[SX];
__device__ float g_b[SX];
__device__ float g_fbg[NSHOT*NT];
__device__ float g_fsc[NSHOT*NT];
__device__ int   g_sloc[NSHOT*2];
__device__ int   g_flag[NSHOT*TPS];   // per-tile completed-step count
__device__ int   g_rec[NSHOT];        // per-shot recording progress

__global__ void zero_kernel() {
    const int n = 16*FIELD + 2*PADC;
    for (int i = blockIdx.x*blockDim.x + threadIdx.x; i < n; i += gridDim.x*blockDim.x)
        g_state[i] = 0.0f;
    int gid = blockIdx.x*blockDim.x + threadIdx.x;
    if (gid < NSHOT*TPS) g_flag[gid] = 0;
    if (gid < NSHOT)     g_rec[gid]  = 0;
}

__global__ void init_kernel(const float* __restrict__ v, const float* __restrict__ sc,
                            const float* __restrict__ amp, const int* __restrict__ sloc) {
    int x = blockIdx.x*blockDim.x + threadIdx.x;   // 0..447
    int y = blockIdx.y;                            // 0..443
    if (x < NN) {
        int vy = min(max(y-22, 0), 399);
        int vx = min(max(x-22, 0), 399);
        float vv = v[vy*400 + vx];
        float ss = (y >= 22 && y < 422 && x >= 22 && x < 422) ? sc[(y-22)*400 + (x-22)] : 0.0f;
        g_v2dt2[y*SX+x] = (vv*DTF)*(vv*DTF);
        g_born [y*SX+x] = 2.0f*vv*ss*DTF*DTF;
    } else if (y < NN) {
        g_v2dt2[y*SX+x] = 0.0f;
        g_born [y*SX+x] = 0.0f;
    }
    if (y == 0) {
        float a = 0.0f, b = 0.0f;
        if (x < NN) {
            float fi = (float)x;
            float f1 = fminf(fmaxf((22.0f - fi)/20.0f, 0.0f), 1.0f);
            float f2 = fminf(fmaxf((fi - 421.0f)/20.0f, 0.0f), 1.0f);
            float frac = fmaxf(f1, f2);
            float sigma = SIGMA_MAX * frac * frac;
            a = expf(-(sigma + ALPHA_F)*DTF);
            b = (sigma > 0.0f) ? sigma/(sigma + ALPHA_F)*(a - 1.0f) : 0.0f;
        }
        g_a[x] = a; g_b[x] = b;
    }
    int lid = y*SX + x;
    if (lid < NSHOT*NT) {
        int s = lid / NT, t = lid % NT;
        int ly = sloc[s*2+0], lx = sloc[s*2+1];
        float vv = v [ly*400 + lx];
        float ss = sc[ly*400 + lx];
        float a  = amp[s*NT + t];
        g_fbg[lid] = (-a * (vv*vv)) * DTF * DTF;
        g_fsc[lid] = ((-2.0f * a) * (vv*ss)) * DTF * DTF;
    }
    if (lid < NSHOT*2) g_sloc[lid] = sloc[lid] + 22;
}

__device__ __forceinline__ void ld4(float* d, const float* p) {
    float4 t = __ldg(reinterpret_cast<const float4*>(p));
    d[0]=t.x; d[1]=t.y; d[2]=t.z; d[3]=t.w;
}
__device__ __forceinline__ void ld4z(float* d, const float* p, bool pred) {
    if (pred) ld4(d, p);
    else { d[0]=0.f; d[1]=0.f; d[2]=0.f; d[3]=0.f; }
}
__device__ __forceinline__ void st4(float* p, const float* d) {
    float4 t; t.x=d[0]; t.y=d[1]; t.z=d[2]; t.w=d[3];
    *reinterpret_cast<float4*>(p) = t;
}

__device__ __forceinline__ void spin_ge(int* addr, int need) {
    while (atomicAdd(addr, 0) < need) __nanosleep(64);
}

// PML-Laplacian for a quad of 4 x-points of one field. wx[12] = w over x0-4..x0+7.
__device__ __forceinline__ void lap_field4(
    const float* __restrict__ w,
    const float* __restrict__ py_o, float* __restrict__ py_n,
    const float* __restrict__ px_o, float* __restrict__ px_n,
    float* __restrict__ zy, float* __restrict__ zx,
    int bi, int y, int x0, bool pmly, bool pmlx,
    const float* wx, float lap[4])
{
    float ym1[4], ym2[4], yp1[4], yp2[4];
    ld4z(ym1, w + bi - SX,   y >= 1);
    ld4z(ym2, w + bi - 2*SX, y >= 2);
    ld4z(yp1, w + bi + SX,   y < NN-1);
    ld4z(yp2, w + bi + 2*SX, y < NN-2);
    float d2y[4], d2x[4];
    #pragma unroll
    for (int j = 0; j < 4; j++) {
        d2y[j] = INVH2*(C20*(ym2[j]+yp2[j]) + C21*(ym1[j]+yp1[j]) + C22*wx[4+j]);
        d2x[j] = INVH2*(C20*(wx[2+j]+wx[6+j]) + C21*(wx[3+j]+wx[5+j]) + C22*wx[4+j]);
        lap[j] = d2y[j] + d2x[j];
    }
    if (pmly) {
        float ym3[4], ym4[4], yp3[4], yp4[4];
        ld4z(ym3, w + bi - 3*SX, y >= 3);
        ld4z(ym4, w + bi - 4*SX, y >= 4);
        ld4z(yp3, w + bi + 3*SX, y < NN-3);
        ld4z(yp4, w + bi + 4*SX, y < NN-4);
        const float* wrow[9] = {ym4, ym3, ym2, ym1, wx+4, yp1, yp2, yp3, yp4};
        const float cc[5] = {C10, C11, 0.0f, C13, C14};
        float dps[4] = {0.f, 0.f, 0.f, 0.f};
        float psn2[4];
        #pragma unroll
        for (int k = 0; k < 5; k++) {
            int jy = y - 2 + k;
            bool ok = (unsigned)jy < (unsigned)NN;
            float aj = ok ? g_a[jy] : 0.0f;
            float bj = ok ? g_b[jy] : 0.0f;
            float pq[4];
            ld4z(pq, py_o + bi + (k-2)*SX, ok);
            #pragma unroll
            for (int j = 0; j < 4; j++) {
                float dw = INVH*(C10*wrow[k][j] + C11*wrow[k+1][j] + C13*wrow[k+3][j] + C14*wrow[k+4][j]);
                float p = aj*pq[j] + bj*dw;
                if (k == 2) psn2[j] = p;
                else        dps[j] += cc[k]*p;
            }
        }
        float zq[4];
        ld4(zq, zy + bi);
        float ay = g_a[y], by = g_b[y];
        #pragma unroll
        for (int j = 0; j < 4; j++) {
            float dpsiy = INVH*dps[j];
            float z = ay*zq[j] + by*(d2y[j] + dpsiy);
            lap[j] += dpsiy + z;
            zq[j] = z;
        }
        st4(py_n + bi, psn2);
        st4(zy + bi, zq);
    }
    if (pmlx) {
        float pxv[12];
        ld4(pxv,   px_o + bi - 4);
        ld4(pxv+4, px_o + bi);
        ld4(pxv+8, px_o + bi + 4);
        float pm[8];   // psi_new at x positions x0-2 .. x0+5
        #pragma unroll
        for (int m = 0; m < 8; m++) {
            int pos = x0 + m - 2;
            int idx = m + 2;          // index into 12-wide local windows
            pm[m] = 0.0f;
            if ((unsigned)pos < (unsigned)NN) {
                float dw = INVH*(C10*wx[idx-2] + C11*wx[idx-1] + C13*wx[idx+1] + C14*wx[idx+2]);
                pm[m] = g_a[pos]*pxv[idx] + g_b[pos]*dw;
            }
        }
        float zq[4], pnew[4];
        ld4(zq, zx + bi);
        #pragma unroll
        for (int j = 0; j < 4; j++) {
            float dpsix = INVH*(C10*pm[j] + C11*pm[j+1] + C13*pm[j+3] + C14*pm[j+4]);
            float z = g_a[x0+j]*zq[j] + g_b[x0+j]*(d2x[j] + dpsix);
            lap[j] += dpsix + z;
            zq[j] = z;
            pnew[j] = pm[j+2];
        }
        st4(px_n + bi, pnew);
        st4(zx + bi, zq);
    }
}

// Software-pipelined step: triggers PDL launch-completion at entry so the next
// step's blocks dispatch into this step's idle tail; ordering is enforced by
// per-tile flags (3x3 neighborhood, stencil reach 4 <= tile 8x128) plus a
// per-shot recording flag protecting the parity being recorded.
__global__ void __launch_bounds__(256, 4) step_kernel(
    const int* __restrict__ rloc, const int* __restrict__ brloc,
    float* __restrict__ out, int t)
{
    cudaTriggerProgrammaticLaunchCompletion();

    const int p = t & 1, q = p ^ 1;
    float* base = g_state + PADC;
    const float* wc    = base + p*FIELD;        float* wn    = base + q*FIELD;
    const float* wcs   = base + (2+p)*FIELD;    float* wns   = base + (2+q)*FIELD;
    const float* pyb_o = base + (4+p)*FIELD;    float* pyb_n = base + (4+q)*FIELD;
    const float* pxb_o = base + (6+p)*FIELD;    float* pxb_n = base + (6+q)*FIELD;
    const float* pys_o = base + (8+p)*FIELD;    float* pys_n = base + (8+q)*FIELD;
    const float* pxs_o = base + (10+p)*FIELD;   float* pxs_n = base + (10+q)*FIELD;
    float* zyb = base + 12*FIELD;  float* zxb = base + 13*FIELD;
    float* zys = base + 14*FIELD;  float* zxs = base + 15*FIELD;

    const int s  = blockIdx.z;
    const int yb = blockIdx.y, xb = blockIdx.x;
    const int tileId = s*TPS + yb*4 + xb;
    const int sy = g_sloc[s*2], sxp = g_sloc[s*2+1];
    const int tid = threadIdx.y*32 + threadIdx.x;
    const bool isRec = (xb == 0 && yb == 0);

    const int R = 4*(t+1);   // domain-of-dependence radius (exact zero outside)
    bool tilePruned = false;
    if (R < NN) {
        int ty0 = yb*8, tx0 = xb*128;
        tilePruned = (ty0 > sy+R || ty0+7 < sy-R || tx0 > sxp+R || tx0+127 < sxp-R);
    }

    // ---- dependency waits (data-driven; replaces the grid boundary) ----
    if (t > 0) {
        if (!tilePruned) {
            if (tid < 9) {           // 3x3 tile neighborhood finished step t-1
                int ny = min(max(yb + tid/3 - 1, 0), 55);
                int nx = min(max(xb + tid%3 - 1, 0), 3);
                spin_ge(&g_flag[s*TPS + ny*4 + nx], t);
            }
            if (tid == 16)           // recording of the parity we overwrite is done
                spin_ge(&g_rec[s], t-1);
        }
        if (isRec && tid < TPS)      // recording needs the whole shot at step t-1
            spin_ge(&g_flag[s*TPS + tid], t);
    }
    __threadfence();   // CCTL.IVALL: invalidate L1 so post-wait loads are fresh
    __syncthreads();

    // ---- fused receiver recording of step t-1 ----
    if (t > 0 && isRec) {
        if (tid < NRECV) {
            int k = s*NRECV + tid;
            int ry = brloc[k*2] + 22, rx = brloc[k*2+1] + 22;
            out[OUT_RECBG + k*NT + (t-1)] = __ldg(wc + s*FS + ry*SX + rx);
        } else if (tid < 2*NRECV) {
            int k = s*NRECV + (tid - NRECV);
            int ry = rloc[k*2] + 22, rx = rloc[k*2+1] + 22;
            out[OUT_RECSC + k*NT + (t-1)] = __ldg(wcs + s*FS + ry*SX + rx);
        }
    }

    // ---- compute (predicated; no early returns so all threads reach sync) ----
    const int qx = xb*32 + threadIdx.x;
    const int y  = yb*8  + threadIdx.y;
    const int x0 = qx * 4;
    bool active = !tilePruned && (qx <= 110) && (y < NN);
    if (active && R < NN) {
        if (y > sy+R || y < sy-R || x0 > sxp+R || x0+3 < sxp-R) active = false;
    }
    if (active) {
        const int bi = s*FS + y*SX + x0;
        const bool pmly = (y  < 24) || (y  >= 420);
        const bool pmlx = (x0 < 24) || (x0 >= 420);

        float lap[4];
        {
            float wxb[12];
            ld4(wxb,   wc + bi - 4);
            ld4(wxb+4, wc + bi);
            ld4(wxb+8, wc + bi + 4);
            lap_field4(wc, pyb_o, pyb_n, pxb_o, pxb_n, zyb, zxb, bi, y, x0, pmly, pmlx, wxb, lap);
            float v2q[4], wpo[4], newv[4];
            ld4(v2q, g_v2dt2 + y*SX + x0);
            ld4(wpo, wn + bi);
            #pragma unroll
            for (int j = 0; j < 4; j++)
                newv[j] = v2q[j]*lap[j] + 2.0f*wxb[4+j] - wpo[j];
            if (y == sy && x0 == (sxp & ~3))
                newv[sxp & 3] += g_fbg[s*NT + t];
            st4(wn + bi, newv);
        }
        {
            float wxs[12];
            ld4(wxs,   wcs + bi - 4);
            ld4(wxs+4, wcs + bi);
            ld4(wxs+8, wcs + bi + 4);
            float laps[4];
            lap_field4(wcs, pys_o, pys_n, pxs_o, pxs_n, zys, zxs, bi, y, x0, pmly, pmlx, wxs, laps);
            float v2q[4], bornq[4], wpos[4], news[4];
            ld4(v2q,   g_v2dt2 + y*SX + x0);
            ld4(bornq, g_born  + y*SX + x0);
            ld4(wpos,  wns + bi);
            #pragma unroll
            for (int j = 0; j < 4; j++)
                news[j] = v2q[j]*laps[j] + 2.0f*wxs[4+j] - wpos[j] + bornq[j]*lap[j];
            if (y == sy && x0 == (sxp & ~3))
                news[sxp & 3] += g_fsc[s*NT + t];
            st4(wns + bi, news);
        }
    }

    // ---- publish completion ----
    __threadfence();
    __syncthreads();
    if (tid == 0) {
        atomicMax(&g_flag[tileId], t + 1);
        if (isRec && t > 0) atomicMax(&g_rec[s], t);
    }
}

__global__ void final_kernel(const int* __restrict__ rloc, const int* __restrict__ brloc,
                             float* __restrict__ out)
{
    const float* wb = g_state + PADC + 0*FIELD;
    const float* ws = g_state + PADC + 2*FIELD;
    int idx = blockIdx.x*blockDim.x + threadIdx.x;
    const int tot = NSHOT*444*444;
    if (idx < tot) {
        int s = idx / (444*444);
        int r = idx % (444*444);
        int y = r / 444, x = r % 444;
        out[idx]          = wb[s*FS + y*SX + x];
        out[OUT_SC + idx] = ws[s*FS + y*SX + x];
    }
    if (idx < 2*NSHOT*NRECV) {
        int which = idx / (NSHOT*NRECV);
        int k     = idx % (NSHOT*NRECV);
        int s = k / NRECV;
        if (which == 0) {
            int ry = brloc[k*2] + 22, rx = brloc[k*2+1] + 22;
            out[OUT_RECBG + k*NT + (NT-1)] = wb[s*FS + ry*SX + rx];
        } else {
            int ry = rloc[k*2] + 22, rx = rloc[k*2+1] + 22;
            out[OUT_RECSC + k*NT + (NT-1)] = ws[s*FS + ry*SX + rx];
        }
    }
}

extern "C" void kernel_launch(void* const* d_in, const int* in_sizes, int n_in,
                              void* d_out, int out_size) {
    const float* v     = (const float*)d_in[0];
    const float* sc    = (const float*)d_in[1];
    const float* amp   = (const float*)d_in[2];
    const int*   sloc  = (const int*)  d_in[3];
    const int*   rloc  = (const int*)  d_in[4];
    const int*   brloc = (const int*)  d_in[5];
    float* out = (float*)d_out;

    zero_kernel<<<2048, 256>>>();
    {
        dim3 b(64, 1), g(7, 444);
        init_kernel<<<g, b>>>(v, sc, amp, sloc);
    }
    {
        // All on the default stream. PSS attr lets each step start dispatching
        // once the previous step's blocks have all STARTED (early trigger);
        // data ordering is enforced by the in-kernel flags.
        cudaLaunchAttribute attrs[1];
        attrs[0].id = cudaLaunchAttributeProgrammaticStreamSerialization;
        attrs[0].val.programmaticStreamSerializationAllowed = 1;

        cudaLaunchConfig_t cfg = {};
        cfg.gridDim  = dim3(4, 56, NSHOT);   // constant grid (proven critical)
        cfg.blockDim = dim3(32, 8);
        cfg.dynamicSmemBytes = 0;
        cfg.stream = 0;
        cfg.attrs = attrs;
        cfg.numAttrs = 1;

        for (int t = 0; t < NT; t++)
            cudaLaunchKernelEx(&cfg, step_kernel, rloc, brloc, out, t);
    }
    // Plain launch: full stream dependency on the last step.
    final_kernel<<<(NSHOT*444*444 + 255)/256, 256>>>(rloc, brloc, out);
}